// round 3
// baseline (speedup 1.0000x reference)
#include <cuda_runtime.h>
#include <cuda_bf16.h>
#include <math.h>

#define H_DIM     2048
#define NV        32
#define NK        16
#define DK        128
#define DV        128
#define CONV_K    4
#define KEY_DIM   2048
#define VALUE_DIM 4096
#define CONV_DIM  8192
#define TOTAL_GEMV_ROWS (CONV_DIM + VALUE_DIM + NV + NV)   // 12352

// Scratch (__device__ globals; allocation-free contract)
__device__ float g_conv_out[CONV_DIM];
__device__ float g_z[VALUE_DIM];
__device__ float g_b[NV];
__device__ float g_a[NV];
__device__ float g_kn[NV][DK];
__device__ float g_qns[NV][DK];
__device__ float g_gexp[NV];
__device__ float g_beta[NV];
__device__ float g_kvp[4][NV][DK];    // kv partials per DK quarter
__device__ float g_corep[2][NV][DK];  // core partials per DK half
__device__ float g_xn[VALUE_DIM];
__device__ unsigned g_barA[8];        // zero-initialized
__device__ unsigned g_barD[8];

__device__ __forceinline__ float warp_sum(float v) {
    #pragma unroll
    for (int o = 16; o; o >>= 1) v += __shfl_xor_sync(0xffffffffu, v, o);
    return v;
}

// Self-resetting grid-wide spin barrier (safe across graph replays).
__device__ __forceinline__ void grid_barrier(int idx, unsigned nctas) {
    __syncthreads();
    if (threadIdx.x == 0) {
        __threadfence();
        atomicAdd(&g_barA[idx], 1u);
        volatile unsigned* pa = &g_barA[idx];
        while (*pa < nctas) __nanosleep(64);
        __threadfence();
        unsigned d = atomicAdd(&g_barD[idx], 1u);
        if (d + 1 == nctas) {          // last departer resets for next replay
            g_barA[idx] = 0;
            __threadfence();
            g_barD[idx] = 0;
        }
    }
    __syncthreads();
}

__global__ void __launch_bounds__(256, 4) k_fused(
    const float* __restrict__ x_in,
    const float* __restrict__ conv_state,
    const float* __restrict__ rec_in,
    const float* __restrict__ conv_w,
    const float* __restrict__ qkv_w,
    const float* __restrict__ z_w,
    const float* __restrict__ b_w,
    const float* __restrict__ a_w,
    const float* __restrict__ ow,
    const float* __restrict__ dt_bias,
    const float* __restrict__ A_log,
    const float* __restrict__ norm_w,
    float* __restrict__ out_hidden,
    float* __restrict__ out_cs,
    float* __restrict__ out_rec)
{
    __shared__ float sbuf[4096 + 32];
    const int tid  = threadIdx.x;
    const int warp = tid >> 5;
    const int lane = tid & 31;
    const unsigned G = gridDim.x;

    // ===================== P1: input projections + conv ====================
    for (int i = tid; i < H_DIM; i += 256) sbuf[i] = x_in[i];
    __syncthreads();

    {
        const int totalWarps = G * 8;
        const float4* __restrict__ x4 = (const float4*)sbuf;
        for (int r = blockIdx.x * 8 + warp; r < TOTAL_GEMV_ROWS; r += totalWarps) {
            const float* w;
            if      (r < CONV_DIM)                  w = qkv_w + (size_t)r * H_DIM;
            else if (r < CONV_DIM + VALUE_DIM)      w = z_w   + (size_t)(r - CONV_DIM) * H_DIM;
            else if (r < CONV_DIM + VALUE_DIM + NV) w = b_w   + (size_t)(r - CONV_DIM - VALUE_DIM) * H_DIM;
            else                                    w = a_w   + (size_t)(r - CONV_DIM - VALUE_DIM - NV) * H_DIM;

            const float4* __restrict__ w4 = (const float4*)w;
            float acc = 0.f;
            #pragma unroll 4
            for (int i = lane; i < H_DIM / 4; i += 32) {
                float4 a4 = w4[i];
                float4 b4 = x4[i];
                acc += a4.x * b4.x + a4.y * b4.y + a4.z * b4.z + a4.w * b4.w;
            }
            acc = warp_sum(acc);
            if (lane == 0) {
                if (r < CONV_DIM) {
                    float cs1 = conv_state[r * 4 + 1];
                    float cs2 = conv_state[r * 4 + 2];
                    float cs3 = conv_state[r * 4 + 3];
                    float s = cs1 * conv_w[r * 4 + 0] + cs2 * conv_w[r * 4 + 1]
                            + cs3 * conv_w[r * 4 + 2] + acc * conv_w[r * 4 + 3];
                    g_conv_out[r] = s / (1.f + expf(-s));
                    ((float4*)out_cs)[r] = make_float4(cs1, cs2, cs3, acc);
                } else if (r < CONV_DIM + VALUE_DIM) {
                    g_z[r - CONV_DIM] = acc;
                } else if (r < CONV_DIM + VALUE_DIM + NV) {
                    g_b[r - CONV_DIM - VALUE_DIM] = acc;
                } else {
                    g_a[r - CONV_DIM - VALUE_DIM - NV] = acc;
                }
            }
        }
    }
    grid_barrier(0, G);

    // ============ P2: per-head norms/gates + kv partials (128 CTAs) ========
    for (int c = blockIdx.x; c < 128; c += G) {
        const int h = c >> 2, qtr = c & 3, kvh = h >> 1;
        const int t = tid & 127, sub = tid >> 7;

        float qraw = 0.f, kraw = 0.f;
        if (tid < 128) {
            qraw = g_conv_out[kvh * DK + t];
            kraw = g_conv_out[KEY_DIM + kvh * DK + t];
            float sq = warp_sum(qraw * qraw);
            float sk = warp_sum(kraw * kraw);
            if (lane == 0) { sbuf[4096 + warp] = sq; sbuf[4096 + 8 + warp] = sk; }
        }
        if (qtr == 0 && tid == 128) {   // one thread: gates
            float bv = g_b[h];
            float av = g_a[h] + dt_bias[h];
            float sp = (av > 20.f) ? av : log1pf(expf(av));
            g_gexp[h] = expf(-expf(A_log[h]) * sp);
            g_beta[h] = 1.f / (1.f + expf(-bv));
        }
        __syncthreads();
        if (tid < 128) {
            float sumq = sbuf[4096] + sbuf[4097] + sbuf[4098] + sbuf[4099];
            float sumk = sbuf[4104] + sbuf[4105] + sbuf[4106] + sbuf[4107];
            float kn_t = kraw * rsqrtf(sumk + 1e-6f);
            sbuf[t] = kn_t;
            if (qtr == 0) {
                g_kn[h][t]  = kn_t;
                g_qns[h][t] = qraw * rsqrtf(sumq + 1e-6f) * 0.08838834764831845f;
            }
        }
        __syncthreads();

        const float* __restrict__ rh = rec_in + (size_t)h * DK * DV;
        float kv = 0.f;
        const int kk0 = qtr * 32 + sub * 16;
        #pragma unroll
        for (int j = 0; j < 16; j++) {
            int kk = kk0 + j;
            kv += rh[kk * DV + t] * sbuf[kk];
        }
        sbuf[128 + sub * 128 + t] = kv;
        __syncthreads();
        if (tid < 128) g_kvp[qtr][h][t] = sbuf[128 + t] + sbuf[256 + t];
        __syncthreads();
    }
    grid_barrier(1, G);

    // ============ P3: rec update + core partials (64 CTAs, L2-hot) =========
    for (int c = blockIdx.x; c < 64; c += G) {
        const int h = c >> 1, half = c & 1;
        const int t = tid & 127, sub = tid >> 7;

        if (tid < 64) {
            int kk = half * 64 + tid;
            sbuf[tid]      = g_kn[h][kk];
            sbuf[64 + tid] = g_qns[h][kk];
        }
        __syncthreads();

        const float gexp = g_gexp[h], beta = g_beta[h];
        float kv = g_kvp[0][h][t] + g_kvp[1][h][t] + g_kvp[2][h][t] + g_kvp[3][h][t];
        float v  = g_conv_out[2 * KEY_DIM + h * DV + t];
        float dl = (v - kv * gexp) * beta;

        const float* __restrict__ rh = rec_in  + (size_t)h * DK * DV;
        float*       __restrict__ ro = out_rec + (size_t)h * DK * DV;
        float core = 0.f;
        const int kkb = half * 64 + sub * 32;
        #pragma unroll 8
        for (int j = 0; j < 32; j++) {
            int kk = kkb + j;
            int si = sub * 32 + j;
            float rn = rh[kk * DV + t] * gexp + sbuf[si] * dl;
            ro[kk * DV + t] = rn;
            core += rn * sbuf[64 + si];
        }
        sbuf[128 + sub * 128 + t] = core;
        __syncthreads();
        if (tid < 128) g_corep[half][h][t] = sbuf[128 + t] + sbuf[256 + t];
        __syncthreads();
    }
    grid_barrier(2, G);

    // ============ P4: RMSNorm + silu(z) gate (32 CTAs) =====================
    for (int c = blockIdx.x; c < 32; c += G) {
        const int h = c, t = tid & 127;
        float core = 0.f;
        if (tid < 128) {
            core = g_corep[0][h][t] + g_corep[1][h][t];
            float c2 = warp_sum(core * core);
            if (lane == 0) sbuf[4096 + warp] = c2;
        }
        __syncthreads();
        if (tid < 128) {
            float var = (sbuf[4096] + sbuf[4097] + sbuf[4098] + sbuf[4099]) * (1.f / 128.f);
            float zv  = g_z[h * DV + t];
            g_xn[h * DV + t] = core * rsqrtf(var + 1e-6f) * norm_w[t]
                             * (zv / (1.f + expf(-zv)));
        }
        __syncthreads();
    }
    grid_barrier(3, G);

    // ============ P5: out_proj GEMV (2 warps per row) ======================
    for (int i = tid; i < VALUE_DIM; i += 256) sbuf[i] = g_xn[i];
    __syncthreads();

    for (int rb = blockIdx.x; rb < 512; rb += G) {
        const int r    = rb * 4 + (warp >> 1);
        const int half = warp & 1;
        const float4* __restrict__ w4 = (const float4*)(ow + (size_t)r * VALUE_DIM + half * 2048);
        const float4* __restrict__ v4 = (const float4*)(sbuf + half * 2048);
        float acc0 = 0.f, acc1 = 0.f;
        #pragma unroll 8
        for (int i = lane; i < 256; i += 32) {
            float4 a0 = w4[i];
            float4 a1 = w4[i + 256];
            float4 b0 = v4[i];
            float4 b1 = v4[i + 256];
            acc0 += a0.x * b0.x + a0.y * b0.y + a0.z * b0.z + a0.w * b0.w;
            acc1 += a1.x * b1.x + a1.y * b1.y + a1.z * b1.z + a1.w * b1.w;
        }
        float acc = warp_sum(acc0 + acc1);
        if (lane == 0) sbuf[4096 + warp] = acc;
        __syncthreads();
        if (lane == 0 && half == 0)
            out_hidden[r] = sbuf[4096 + warp] + sbuf[4096 + warp + 1];
        __syncthreads();
    }
}

extern "C" void kernel_launch(void* const* d_in, const int* in_sizes, int n_in,
                              void* d_out, int out_size) {
    const float* hidden_in  = (const float*)d_in[0];
    const float* conv_state = (const float*)d_in[1];
    const float* rec_state  = (const float*)d_in[2];
    const float* conv_w     = (const float*)d_in[3];
    const float* qkv_w      = (const float*)d_in[4];
    const float* z_w        = (const float*)d_in[5];
    const float* b_w        = (const float*)d_in[6];
    const float* a_w        = (const float*)d_in[7];
    const float* out_proj_w = (const float*)d_in[8];
    const float* dt_bias    = (const float*)d_in[9];
    const float* A_log      = (const float*)d_in[10];
    const float* norm_w     = (const float*)d_in[11];

    float* out        = (float*)d_out;
    float* out_hidden = out;
    float* out_cs     = out + H_DIM;
    float* out_rec    = out + H_DIM + CONV_DIM * CONV_K;

    int nsm = 0;
    cudaDeviceGetAttribute(&nsm, cudaDevAttrMultiProcessorCount, 0);
    if (nsm <= 0) nsm = 148;
    int grid = nsm * 4;   // co-resident by construction (launch_bounds(256,4))

    k_fused<<<grid, 256>>>(hidden_in, conv_state, rec_state, conv_w,
                           qkv_w, z_w, b_w, a_w, out_proj_w,
                           dt_bias, A_log, norm_w,
                           out_hidden, out_cs, out_rec);
}

// round 4
// speedup vs baseline: 1.0462x; 1.0462x over previous
#include <cuda_runtime.h>
#include <cuda_bf16.h>
#include <math.h>

#define H_DIM     2048
#define NV        32
#define NK        16
#define DK        128
#define DV        128
#define CONV_K    4
#define KEY_DIM   2048
#define VALUE_DIM 4096
#define CONV_DIM  8192
#define TOTAL_GEMV_ROWS (CONV_DIM + VALUE_DIM + NV + NV)   // 12352

// Scratch (__device__ globals; allocation-free contract)
__device__ float g_conv_out[CONV_DIM];
__device__ float g_z[VALUE_DIM];
__device__ float g_b[NV];
__device__ float g_a[NV];
__device__ float g_xn[VALUE_DIM];

__device__ __forceinline__ float warp_sum(float v) {
    #pragma unroll
    for (int o = 16; o; o >>= 1) v += __shfl_xor_sync(0xffffffffu, v, o);
    return v;
}

__device__ __forceinline__ void l2_prefetch(const void* p) {
    asm volatile("prefetch.global.L2 [%0];" :: "l"(p));
}

// ---------------------------------------------------------------------------
// Kernel A: fused input projections (qkv/z/b/a) + conv epilogue.
// R1 loop shape (single accumulator, unroll 4, 36 regs). Triggers PDL early.
// ---------------------------------------------------------------------------
__global__ void __launch_bounds__(256) k_gemv_conv(
    const float* __restrict__ x_in,
    const float* __restrict__ qkv_w,
    const float* __restrict__ z_w,
    const float* __restrict__ b_w,
    const float* __restrict__ a_w,
    const float* __restrict__ conv_state,
    const float* __restrict__ conv_w,
    float* __restrict__ out_conv_state)
{
    __shared__ float xs[H_DIM];
    for (int i = threadIdx.x; i < H_DIM; i += blockDim.x) xs[i] = x_in[i];
    __syncthreads();

    // Let dependent kernel B launch while we stream 96 MB of weights.
    cudaTriggerProgrammaticLaunchCompletion();

    const int warp = threadIdx.x >> 5;
    const int lane = threadIdx.x & 31;
    const int r = blockIdx.x * 8 + warp;
    if (r >= TOTAL_GEMV_ROWS) return;

    const float* w;
    if      (r < CONV_DIM)                  w = qkv_w + (size_t)r * H_DIM;
    else if (r < CONV_DIM + VALUE_DIM)      w = z_w   + (size_t)(r - CONV_DIM) * H_DIM;
    else if (r < CONV_DIM + VALUE_DIM + NV) w = b_w   + (size_t)(r - CONV_DIM - VALUE_DIM) * H_DIM;
    else                                    w = a_w   + (size_t)(r - CONV_DIM - VALUE_DIM - NV) * H_DIM;

    const float4* __restrict__ w4 = (const float4*)w;
    const float4* __restrict__ x4 = (const float4*)xs;
    float acc = 0.f;
    #pragma unroll 4
    for (int i = lane; i < H_DIM / 4; i += 32) {
        float4 a4 = w4[i];
        float4 b4 = x4[i];
        acc += a4.x * b4.x + a4.y * b4.y + a4.z * b4.z + a4.w * b4.w;
    }
    acc = warp_sum(acc);

    if (lane == 0) {
        if (r < CONV_DIM) {
            float cs1 = conv_state[r * 4 + 1];
            float cs2 = conv_state[r * 4 + 2];
            float cs3 = conv_state[r * 4 + 3];
            float s = cs1 * conv_w[r * 4 + 0] + cs2 * conv_w[r * 4 + 1]
                    + cs3 * conv_w[r * 4 + 2] + acc * conv_w[r * 4 + 3];
            g_conv_out[r] = s / (1.f + expf(-s));
            ((float4*)out_conv_state)[r] = make_float4(cs1, cs2, cs3, acc);
        } else if (r < CONV_DIM + VALUE_DIM) {
            g_z[r - CONV_DIM] = acc;
        } else if (r < CONV_DIM + VALUE_DIM + NV) {
            g_b[r - CONV_DIM - VALUE_DIM] = acc;
        } else {
            g_a[r - CONV_DIM - VALUE_DIM - NV] = acc;
        }
    }
}

// ---------------------------------------------------------------------------
// Kernel B: per-head delta rule. 32 blocks x 512 threads (PDL secondary).
// Prefetches its rec head into L2 BEFORE the grid dependency sync.
// ---------------------------------------------------------------------------
__global__ void __launch_bounds__(512) k_delta(
    const float* __restrict__ rec_in,
    const float* __restrict__ dt_bias,
    const float* __restrict__ A_log,
    const float* __restrict__ norm_w,
    float* __restrict__ rec_out)
{
    const int h    = blockIdx.x;
    const int tid  = threadIdx.x;
    const int q    = tid >> 7;            // kk quarter 0..3
    const int t    = tid & 127;           // v column
    const int warp = tid >> 5, lane = tid & 31;

    // --- pre-sync: pull this head's 64 KB of rec into L2 (indep. of A) ---
    {
        const char* base = (const char*)(rec_in + (size_t)h * DK * DV);
        l2_prefetch(base + tid * 128);    // 512 threads x 128B = 64 KB
    }
    cudaTriggerProgrammaticLaunchCompletion();   // let C launch + prefetch
    cudaGridDependencySynchronize();             // wait for A's results

    __shared__ float qn[DK], kn[DK];
    __shared__ float red[16];
    __shared__ float kvp[4][DK];
    __shared__ float crp[4][DK];
    __shared__ float s_gexp, s_beta;

    const int kvh = h >> 1;               // vpk = 2
    float qraw = g_conv_out[kvh * DK + t];
    float kraw = g_conv_out[KEY_DIM + kvh * DK + t];
    float vval = g_conv_out[2 * KEY_DIM + h * DV + t];

    float sq = warp_sum(qraw * qraw);
    float sk = warp_sum(kraw * kraw);
    if (lane == 0) red[warp] = sq;
    if (tid == 0) {
        float bv = g_b[h];
        float av = g_a[h] + dt_bias[h];
        float sp = (av > 20.f) ? av : log1pf(expf(av));
        s_gexp = expf(-expf(A_log[h]) * sp);
        s_beta = 1.f / (1.f + expf(-bv));
    }
    __syncthreads();
    float sumq = red[q * 4 + 0] + red[q * 4 + 1] + red[q * 4 + 2] + red[q * 4 + 3];
    __syncthreads();
    if (lane == 0) red[warp] = sk;
    __syncthreads();
    float sumk = red[q * 4 + 0] + red[q * 4 + 1] + red[q * 4 + 2] + red[q * 4 + 3];
    if (q == 0) {
        qn[t] = qraw * rsqrtf(sumq + 1e-6f) * 0.08838834764831845f;
        kn[t] = kraw * rsqrtf(sumk + 1e-6f);
    }
    __syncthreads();
    const float gexp = s_gexp, beta = s_beta;

    const float* __restrict__ rh = rec_in  + (size_t)h * DK * DV;
    float*       __restrict__ ro = rec_out + (size_t)h * DK * DV;
    const int kk0 = q * 32;

    float kv = 0.f;
    #pragma unroll 8
    for (int j = 0; j < 32; j++) {
        int kk = kk0 + j;
        kv += rh[kk * DV + t] * kn[kk];
    }
    kvp[q][t] = kv;
    __syncthreads();
    float kvsum = (kvp[0][t] + kvp[1][t] + kvp[2][t] + kvp[3][t]) * gexp;
    const float dl = (vval - kvsum) * beta;

    float core = 0.f;
    #pragma unroll 8
    for (int j = 0; j < 32; j++) {
        int kk = kk0 + j;
        float rn = rh[kk * DV + t] * gexp + kn[kk] * dl;
        ro[kk * DV + t] = rn;
        core += rn * qn[kk];
    }
    crp[q][t] = core;
    __syncthreads();

    if (q == 0) {
        float c = crp[0][t] + crp[1][t] + crp[2][t] + crp[3][t];
        float c2 = warp_sum(c * c);
        if (lane == 0) red[warp] = c2;
        __syncthreads();
        float var = (red[0] + red[1] + red[2] + red[3]) * (1.f / 128.f);
        float zv = g_z[h * DV + t];
        g_xn[h * DV + t] = c * rsqrtf(var + 1e-6f) * norm_w[t]
                         * (zv / (1.f + expf(-zv)));
    }
}

// ---------------------------------------------------------------------------
// Kernel C: out_proj GEMV (PDL secondary). Prefetches its weight rows into
// L2 pre-sync, then streams them (L2 hits for the prefetched part).
// ---------------------------------------------------------------------------
__global__ void __launch_bounds__(256) k_outproj(
    const float* __restrict__ ow,
    float* __restrict__ out_hidden)
{
    const int warp = threadIdx.x >> 5;
    const int lane = threadIdx.x & 31;
    const int r = blockIdx.x * 8 + warp;

    // --- pre-sync: prefetch this block's 8 rows (128 KB) into L2 ---
    {
        const char* base = (const char*)(ow + (size_t)(blockIdx.x * 8) * VALUE_DIM);
        #pragma unroll
        for (int i = 0; i < 4; i++)
            l2_prefetch(base + (threadIdx.x + i * 256) * 128);  // 256t x 4 x 128B
    }
    cudaGridDependencySynchronize();   // wait for B's g_xn

    __shared__ float vs[VALUE_DIM];
    for (int i = threadIdx.x; i < VALUE_DIM; i += blockDim.x) vs[i] = g_xn[i];
    __syncthreads();

    const float4* __restrict__ w4 = (const float4*)(ow + (size_t)r * VALUE_DIM);
    const float4* __restrict__ v4 = (const float4*)vs;
    float acc = 0.f;
    #pragma unroll 4
    for (int i = lane; i < VALUE_DIM / 4; i += 32) {
        float4 a4 = w4[i];
        float4 b4 = v4[i];
        acc += a4.x * b4.x + a4.y * b4.y + a4.z * b4.z + a4.w * b4.w;
    }
    acc = warp_sum(acc);
    if (lane == 0) out_hidden[r] = acc;
}

// ---------------------------------------------------------------------------
extern "C" void kernel_launch(void* const* d_in, const int* in_sizes, int n_in,
                              void* d_out, int out_size) {
    const float* hidden_in  = (const float*)d_in[0];
    const float* conv_state = (const float*)d_in[1];
    const float* rec_state  = (const float*)d_in[2];
    const float* conv_w     = (const float*)d_in[3];
    const float* qkv_w      = (const float*)d_in[4];
    const float* z_w        = (const float*)d_in[5];
    const float* b_w        = (const float*)d_in[6];
    const float* a_w        = (const float*)d_in[7];
    const float* out_proj_w = (const float*)d_in[8];
    const float* dt_bias    = (const float*)d_in[9];
    const float* A_log      = (const float*)d_in[10];
    const float* norm_w     = (const float*)d_in[11];

    float* out        = (float*)d_out;
    float* out_hidden = out;
    float* out_cs     = out + H_DIM;
    float* out_rec    = out + H_DIM + CONV_DIM * CONV_K;

    // A: plain launch
    k_gemv_conv<<<(TOTAL_GEMV_ROWS + 7) / 8, 256>>>(
        hidden_in, qkv_w, z_w, b_w, a_w, conv_state, conv_w, out_cs);

    // B, C: programmatic dependent launches (overlap launch + prefetch)
    cudaLaunchAttribute attr[1];
    attr[0].id = cudaLaunchAttributeProgrammaticStreamSerialization;
    attr[0].val.programmaticStreamSerializationAllowed = 1;

    {
        cudaLaunchConfig_t cfg = {};
        cfg.gridDim  = dim3(NV, 1, 1);
        cfg.blockDim = dim3(512, 1, 1);
        cfg.attrs = attr;
        cfg.numAttrs = 1;
        cudaLaunchKernelEx(&cfg, k_delta, rec_state, dt_bias, A_log, norm_w, out_rec);
    }
    {
        cudaLaunchConfig_t cfg = {};
        cfg.gridDim  = dim3(H_DIM / 8, 1, 1);
        cfg.blockDim = dim3(256, 1, 1);
        cfg.attrs = attr;
        cfg.numAttrs = 1;
        cudaLaunchKernelEx(&cfg, k_outproj, out_proj_w, out_hidden);
    }
}

// round 5
// speedup vs baseline: 1.2778x; 1.2214x over previous
#include <cuda_runtime.h>
#include <cuda_bf16.h>
#include <math.h>

#define H_DIM     2048
#define NV        32
#define NK        16
#define DK        128
#define DV        128
#define CONV_K    4
#define KEY_DIM   2048
#define VALUE_DIM 4096
#define CONV_DIM  8192
#define TOTAL_GEMV_ROWS (CONV_DIM + VALUE_DIM + NV + NV)   // 12352

// Scratch (__device__ globals; allocation-free contract)
__device__ float g_conv_out[CONV_DIM];
__device__ float g_z[VALUE_DIM];
__device__ float g_b[NV];
__device__ float g_a[NV];
__device__ float g_xn[VALUE_DIM];

__device__ __forceinline__ float warp_sum(float v) {
    #pragma unroll
    for (int o = 16; o; o >>= 1) v += __shfl_xor_sync(0xffffffffu, v, o);
    return v;
}

__device__ __forceinline__ void l2_prefetch(const void* p) {
    asm volatile("prefetch.global.L2 [%0];" :: "l"(p));
}

// Streaming (evict-first) 128-bit load: read-once weight data.
__device__ __forceinline__ float4 ldcs4(const float4* p) {
    float4 r;
    asm volatile("ld.global.cs.v4.f32 {%0,%1,%2,%3}, [%4];"
                 : "=f"(r.x), "=f"(r.y), "=f"(r.z), "=f"(r.w) : "l"(p));
    return r;
}

// ---------------------------------------------------------------------------
// Kernel A: persistent single-wave GEMV over all 12352 projection rows
// + conv shift/silu epilogue. Warp-per-row, rows strided across all warps.
// ---------------------------------------------------------------------------
__global__ void __launch_bounds__(256) k_gemv_conv(
    const float* __restrict__ x_in,
    const float* __restrict__ qkv_w,
    const float* __restrict__ z_w,
    const float* __restrict__ b_w,
    const float* __restrict__ a_w,
    const float* __restrict__ conv_state,
    const float* __restrict__ conv_w,
    float* __restrict__ out_conv_state)
{
    __shared__ float xs[H_DIM];
    for (int i = threadIdx.x; i < H_DIM; i += blockDim.x) xs[i] = x_in[i];
    __syncthreads();

    cudaTriggerProgrammaticLaunchCompletion();

    const int warp = threadIdx.x >> 5;
    const int lane = threadIdx.x & 31;
    const int totalWarps = gridDim.x * 8;
    const float4* __restrict__ x4 = (const float4*)xs;

    for (int r = blockIdx.x * 8 + warp; r < TOTAL_GEMV_ROWS; r += totalWarps) {
        const float* w;
        if      (r < CONV_DIM)                  w = qkv_w + (size_t)r * H_DIM;
        else if (r < CONV_DIM + VALUE_DIM)      w = z_w   + (size_t)(r - CONV_DIM) * H_DIM;
        else if (r < CONV_DIM + VALUE_DIM + NV) w = b_w   + (size_t)(r - CONV_DIM - VALUE_DIM) * H_DIM;
        else                                    w = a_w   + (size_t)(r - CONV_DIM - VALUE_DIM - NV) * H_DIM;

        const float4* __restrict__ w4 = (const float4*)w;
        float acc = 0.f;
        #pragma unroll 4
        for (int i = lane; i < H_DIM / 4; i += 32) {
            float4 a4 = ldcs4(w4 + i);
            float4 b4 = x4[i];
            acc += a4.x * b4.x + a4.y * b4.y + a4.z * b4.z + a4.w * b4.w;
        }
        acc = warp_sum(acc);

        if (lane == 0) {
            if (r < CONV_DIM) {
                float cs1 = conv_state[r * 4 + 1];
                float cs2 = conv_state[r * 4 + 2];
                float cs3 = conv_state[r * 4 + 3];
                float s = cs1 * conv_w[r * 4 + 0] + cs2 * conv_w[r * 4 + 1]
                        + cs3 * conv_w[r * 4 + 2] + acc * conv_w[r * 4 + 3];
                g_conv_out[r] = s / (1.f + expf(-s));
                ((float4*)out_conv_state)[r] = make_float4(cs1, cs2, cs3, acc);
            } else if (r < CONV_DIM + VALUE_DIM) {
                g_z[r - CONV_DIM] = acc;
            } else if (r < CONV_DIM + VALUE_DIM + NV) {
                g_b[r - CONV_DIM - VALUE_DIM] = acc;
            } else {
                g_a[r - CONV_DIM - VALUE_DIM - NV] = acc;
            }
        }
    }
}

// ---------------------------------------------------------------------------
// Kernel B: per-head delta rule. 32 blocks x 512 threads (PDL secondary).
// Prefetches its rec head (2 MB total, reused twice) into L2 pre-sync.
// ---------------------------------------------------------------------------
__global__ void __launch_bounds__(512) k_delta(
    const float* __restrict__ rec_in,
    const float* __restrict__ dt_bias,
    const float* __restrict__ A_log,
    const float* __restrict__ norm_w,
    float* __restrict__ rec_out)
{
    const int h    = blockIdx.x;
    const int tid  = threadIdx.x;
    const int q    = tid >> 7;
    const int t    = tid & 127;
    const int warp = tid >> 5, lane = tid & 31;

    {
        const char* base = (const char*)(rec_in + (size_t)h * DK * DV);
        l2_prefetch(base + tid * 128);
    }
    cudaTriggerProgrammaticLaunchCompletion();
    cudaGridDependencySynchronize();

    __shared__ float qn[DK], kn[DK];
    __shared__ float red[16];
    __shared__ float kvp[4][DK];
    __shared__ float crp[4][DK];
    __shared__ float s_gexp, s_beta;

    const int kvh = h >> 1;
    float qraw = g_conv_out[kvh * DK + t];
    float kraw = g_conv_out[KEY_DIM + kvh * DK + t];
    float vval = g_conv_out[2 * KEY_DIM + h * DV + t];

    float sq = warp_sum(qraw * qraw);
    float sk = warp_sum(kraw * kraw);
    if (lane == 0) red[warp] = sq;
    if (tid == 0) {
        float bv = g_b[h];
        float av = g_a[h] + dt_bias[h];
        float sp = (av > 20.f) ? av : log1pf(expf(av));
        s_gexp = expf(-expf(A_log[h]) * sp);
        s_beta = 1.f / (1.f + expf(-bv));
    }
    __syncthreads();
    float sumq = red[q * 4 + 0] + red[q * 4 + 1] + red[q * 4 + 2] + red[q * 4 + 3];
    __syncthreads();
    if (lane == 0) red[warp] = sk;
    __syncthreads();
    float sumk = red[q * 4 + 0] + red[q * 4 + 1] + red[q * 4 + 2] + red[q * 4 + 3];
    if (q == 0) {
        qn[t] = qraw * rsqrtf(sumq + 1e-6f) * 0.08838834764831845f;
        kn[t] = kraw * rsqrtf(sumk + 1e-6f);
    }
    __syncthreads();
    const float gexp = s_gexp, beta = s_beta;

    const float* __restrict__ rh = rec_in  + (size_t)h * DK * DV;
    float*       __restrict__ ro = rec_out + (size_t)h * DK * DV;
    const int kk0 = q * 32;

    float kv = 0.f;
    #pragma unroll 8
    for (int j = 0; j < 32; j++) {
        int kk = kk0 + j;
        kv += rh[kk * DV + t] * kn[kk];
    }
    kvp[q][t] = kv;
    __syncthreads();
    float kvsum = (kvp[0][t] + kvp[1][t] + kvp[2][t] + kvp[3][t]) * gexp;
    const float dl = (vval - kvsum) * beta;

    float core = 0.f;
    #pragma unroll 8
    for (int j = 0; j < 32; j++) {
        int kk = kk0 + j;
        float rn = rh[kk * DV + t] * gexp + kn[kk] * dl;
        ro[kk * DV + t] = rn;
        core += rn * qn[kk];
    }
    crp[q][t] = core;
    __syncthreads();

    if (q == 0) {
        float c = crp[0][t] + crp[1][t] + crp[2][t] + crp[3][t];
        float c2 = warp_sum(c * c);
        if (lane == 0) red[warp] = c2;
        __syncthreads();
        float var = (red[0] + red[1] + red[2] + red[3]) * (1.f / 128.f);
        float zv = g_z[h * DV + t];
        g_xn[h * DV + t] = c * rsqrtf(var + 1e-6f) * norm_w[t]
                         * (zv / (1.f + expf(-zv)));
    }
}

// ---------------------------------------------------------------------------
// Kernel C: out_proj GEMV (PDL secondary, NO weight prefetch).
// ---------------------------------------------------------------------------
__global__ void __launch_bounds__(256) k_outproj(
    const float* __restrict__ ow,
    float* __restrict__ out_hidden)
{
    cudaGridDependencySynchronize();

    __shared__ float vs[VALUE_DIM];
    for (int i = threadIdx.x; i < VALUE_DIM; i += blockDim.x) vs[i] = g_xn[i];
    __syncthreads();

    const int warp = threadIdx.x >> 5;
    const int lane = threadIdx.x & 31;
    const int r = blockIdx.x * 8 + warp;

    const float4* __restrict__ w4 = (const float4*)(ow + (size_t)r * VALUE_DIM);
    const float4* __restrict__ v4 = (const float4*)vs;
    float acc = 0.f;
    #pragma unroll 4
    for (int i = lane; i < VALUE_DIM / 4; i += 32) {
        float4 a4 = ldcs4(w4 + i);
        float4 b4 = v4[i];
        acc += a4.x * b4.x + a4.y * b4.y + a4.z * b4.z + a4.w * b4.w;
    }
    acc = warp_sum(acc);
    if (lane == 0) out_hidden[r] = acc;
}

// ---------------------------------------------------------------------------
extern "C" void kernel_launch(void* const* d_in, const int* in_sizes, int n_in,
                              void* d_out, int out_size) {
    const float* hidden_in  = (const float*)d_in[0];
    const float* conv_state = (const float*)d_in[1];
    const float* rec_state  = (const float*)d_in[2];
    const float* conv_w     = (const float*)d_in[3];
    const float* qkv_w      = (const float*)d_in[4];
    const float* z_w        = (const float*)d_in[5];
    const float* b_w        = (const float*)d_in[6];
    const float* a_w        = (const float*)d_in[7];
    const float* out_proj_w = (const float*)d_in[8];
    const float* dt_bias    = (const float*)d_in[9];
    const float* A_log      = (const float*)d_in[10];
    const float* norm_w     = (const float*)d_in[11];

    float* out        = (float*)d_out;
    float* out_hidden = out;
    float* out_cs     = out + H_DIM;
    float* out_rec    = out + H_DIM + CONV_DIM * CONV_K;

    int nsm = 0;
    cudaDeviceGetAttribute(&nsm, cudaDevAttrMultiProcessorCount, 0);
    if (nsm <= 0) nsm = 148;

    // A: persistent single wave (7 CTAs/SM co-resident at 36 regs, 8KB smem)
    k_gemv_conv<<<nsm * 7, 256>>>(
        hidden_in, qkv_w, z_w, b_w, a_w, conv_state, conv_w, out_cs);

    cudaLaunchAttribute attr[1];
    attr[0].id = cudaLaunchAttributeProgrammaticStreamSerialization;
    attr[0].val.programmaticStreamSerializationAllowed = 1;

    {
        cudaLaunchConfig_t cfg = {};
        cfg.gridDim  = dim3(NV, 1, 1);
        cfg.blockDim = dim3(512, 1, 1);
        cfg.attrs = attr;
        cfg.numAttrs = 1;
        cudaLaunchKernelEx(&cfg, k_delta, rec_state, dt_bias, A_log, norm_w, out_rec);
    }
    {
        cudaLaunchConfig_t cfg = {};
        cfg.gridDim  = dim3(H_DIM / 8, 1, 1);
        cfg.blockDim = dim3(256, 1, 1);
        cfg.attrs = attr;
        cfg.numAttrs = 1;
        cudaLaunchKernelEx(&cfg, k_outproj, out_proj_w, out_hidden);
    }
}